// round 5
// baseline (speedup 1.0000x reference)
#include <cuda_runtime.h>

#define BATCH   32
#define SDIM    65536
#define RNK     128
#define NDEG    4
#define KSLICES 256
#define KPER    (SDIM / KSLICES)   // 256  -> zs = 256*36*4 = 36,864 B (< 48KB static cap)
#define NTOT    (BATCH * SDIM)     // 2097152
#define RED_BLOCKS 256
#define STILE   32
#define KSGRP   8                  // combine stage-1 groups (32 slices each)

// ---------------- scratch (device globals; no runtime allocation) -------------
__device__ float g_stats[2];
__device__ float g_bsum[RED_BLOCKS];
__device__ float g_bsq[RED_BLOCKS];
__device__ float g_z[NTOT];                                   // normalized x, [B][S]
__device__ float g_partial[NDEG * KSLICES * BATCH * RNK];     // split-K partials (16MB)
__device__ float g_part2[NDEG * KSGRP * BATCH * RNK];         // stage-1 sums
__device__ float g_ht[RNK * BATCH];                           // h transposed [r][b]

// ---------------- packed f32x2 helpers ----------------------------------------
__device__ __forceinline__ unsigned long long pack_dup(float v) {
    unsigned long long r;
    asm("mov.b64 %0, {%1, %1};" : "=l"(r) : "f"(v));
    return r;
}
#define FMA2(acc, a, b) \
    asm("fma.rn.f32x2 %0, %1, %2, %0;" : "+l"(acc) : "l"(a), "l"(b))

// ---------------- 1) per-block reduction of sum / sumsq ----------------------
__global__ void k_reduce(const float* __restrict__ x) {
    float s = 0.f, sq = 0.f;
    const float4* x4 = (const float4*)x;
    const int stride = gridDim.x * blockDim.x;
    for (int i = blockIdx.x * blockDim.x + threadIdx.x; i < NTOT / 4; i += stride) {
        float4 v = x4[i];
        s  += (v.x + v.y) + (v.z + v.w);
        sq += (v.x * v.x + v.y * v.y) + (v.z * v.z + v.w * v.w);
    }
    #pragma unroll
    for (int o = 16; o > 0; o >>= 1) {
        s  += __shfl_down_sync(0xffffffffu, s,  o);
        sq += __shfl_down_sync(0xffffffffu, sq, o);
    }
    __shared__ float ss[8], sqq[8];
    int w = threadIdx.x >> 5, lane = threadIdx.x & 31;
    if (lane == 0) { ss[w] = s; sqq[w] = sq; }
    __syncthreads();
    if (threadIdx.x == 0) {
        float S = 0.f, Q = 0.f;
        #pragma unroll
        for (int j = 0; j < 8; j++) { S += ss[j]; Q += sqq[j]; }
        g_bsum[blockIdx.x] = S;
        g_bsq[blockIdx.x]  = Q;
    }
}

// ---------------- 2) final stats ----------------------------------------------
__global__ void k_stats() {
    int t = threadIdx.x;                 // 256 threads
    float s = g_bsum[t], q = g_bsq[t];
    #pragma unroll
    for (int o = 16; o > 0; o >>= 1) {
        s += __shfl_down_sync(0xffffffffu, s, o);
        q += __shfl_down_sync(0xffffffffu, q, o);
    }
    __shared__ float ss[8], qq[8];
    int w = t >> 5, lane = t & 31;
    if (lane == 0) { ss[w] = s; qq[w] = q; }
    __syncthreads();
    if (t == 0) {
        float S = 0.f, Q = 0.f;
        #pragma unroll
        for (int j = 0; j < 8; j++) { S += ss[j]; Q += qq[j]; }
        g_stats[0] = S;
        g_stats[1] = Q;
    }
}

// ---------------- 3) normalize x -> z -----------------------------------------
__global__ void k_normalize(const float* __restrict__ x,
                            const float* __restrict__ gamma,
                            const float* __restrict__ bnb) {
    const float inv_n = 1.f / (float)NTOT;
    float mean = g_stats[0] * inv_n;
    float var  = g_stats[1] * inv_n - mean * mean;
    float istd = rsqrtf(var + 1e-5f);
    float a = gamma[0] * istd;
    float c = bnb[0] - mean * a;
    int i = blockIdx.x * blockDim.x + threadIdx.x;      // exactly NTOT/4 threads
    float4 v = ((const float4*)x)[i];
    float4 o;
    o.x = fmaf(v.x, a, c);
    o.y = fmaf(v.y, a, c);
    o.z = fmaf(v.z, a, c);
    o.w = fmaf(v.w, a, c);
    ((float4*)g_z)[i] = o;
}

// ---------------- 4) GEMM1 (split-K, packed f32x2) ----------------------------
// 128 threads = one per rank column r. 16 u64 accumulators = 32 batches paired.
// U loads coalesced; z slice staged in smem [k][b], stride 36 (rows 16B aligned,
// broadcast reads so bank pattern irrelevant).
__global__ __launch_bounds__(128) void k_gemm1(const float* __restrict__ U) {
    __shared__ __align__(16) float zs[KPER][36];        // 36,864 B static
    const int n   = blockIdx.y;
    const int ks  = blockIdx.x;
    const int tid = threadIdx.x;

    {   // stage z[b][ks*KPER + k] -> zs[k][b]  (coalesced global reads)
        const float* zsrc = g_z + ks * KPER;
        #pragma unroll
        for (int i = tid; i < BATCH * KPER; i += 128) {
            int b = i >> 8;            // KPER = 256
            int k = i & (KPER - 1);
            zs[k][b] = zsrc[b * SDIM + k];
        }
    }
    __syncthreads();

    const float* Up = U + ((size_t)n * SDIM + (size_t)ks * KPER) * RNK + tid;
    unsigned long long acc[BATCH / 2];
    #pragma unroll
    for (int j = 0; j < BATCH / 2; j++) acc[j] = 0ull;

    #pragma unroll 4
    for (int k = 0; k < KPER; k++) {
        unsigned long long uu = pack_dup(Up[(size_t)k * RNK]);
        const ulonglong2* zrow = (const ulonglong2*)(&zs[k][0]);
        #pragma unroll
        for (int q = 0; q < 8; q++) {
            ulonglong2 z2 = zrow[q];
            FMA2(acc[2 * q],     uu, z2.x);
            FMA2(acc[2 * q + 1], uu, z2.y);
        }
    }

    float* outp = g_partial + (size_t)(n * KSLICES + ks) * (BATCH * RNK) + tid;
    #pragma unroll
    for (int j = 0; j < BATCH / 2; j++) {
        float2 v = *(float2*)&acc[j];
        outp[(2 * j) * RNK]     = v.x;
        outp[(2 * j + 1) * RNK] = v.y;
    }
}

// ---------------- 5a) combine stage 1: sum 32 k-slices ------------------------
__global__ void k_combine1() {
    const int idx = blockIdx.x * blockDim.x + threadIdx.x;  // 0..4095 (b*RNK+r)
    const int g   = blockIdx.y;                              // 0..KSGRP-1
    #pragma unroll
    for (int n = 0; n < NDEG; n++) {
        const float* p = g_partial + idx
                       + (size_t)(n * KSLICES + g * (KSLICES / KSGRP)) * (BATCH * RNK);
        float t = 0.f;
        #pragma unroll 8
        for (int ks = 0; ks < KSLICES / KSGRP; ks++)
            t += p[(size_t)ks * (BATCH * RNK)];
        g_part2[(n * KSGRP + g) * (BATCH * RNK) + idx] = t;
    }
}

// ---------------- 5b) combine stage 2 + degree-4 CCP recurrence ---------------
__global__ void k_combine2() {
    int idx = blockIdx.x * blockDim.x + threadIdx.x;    // 4096 threads = b*RNK+r
    float t[NDEG];
    #pragma unroll
    for (int n = 0; n < NDEG; n++) {
        float s = 0.f;
        #pragma unroll
        for (int g = 0; g < KSGRP; g++)
            s += g_part2[(n * KSGRP + g) * (BATCH * RNK) + idx];
        t[n] = s;
    }
    float h = t[0];
    h = fmaf(t[1], h, h);
    h = fmaf(t[2], h, h);
    h = fmaf(t[3], h, h);
    int b = idx >> 7, r = idx & 127;
    g_ht[r * BATCH + b] = h;                            // store transposed [r][b]
}

// ---------------- 6) GEMM2: out[b][s] = sum_r h[b][r]*C[s][r] + beta[s] -------
// Block: 32 s x all 32 b, 64 threads: sl=tid&31 (one s), bg=tid>>5 (16 b each).
// Static smem ~32.9 KB. Packed f32x2 along b.
__global__ __launch_bounds__(64) void k_gemm2(const float* __restrict__ Cm,
                                              const float* __restrict__ beta,
                                              float* __restrict__ out) {
    __shared__ __align__(16) float cs[STILE][129];      // padded, conflict-free
    __shared__ __align__(16) float hs[RNK][BATCH];      // [r][b], broadcast reads
    const int tid = threadIdx.x;
    const int s0  = blockIdx.x * STILE;

    // load C tile (coalesced float4)
    #pragma unroll
    for (int i = tid; i < STILE * RNK / 4; i += 64) {
        int s  = i >> 5;                   // 32 float4 per 128-float row
        int rq = i & 31;
        float4 v = ((const float4*)(Cm + (size_t)(s0 + s) * RNK))[rq];
        int r = rq * 4;
        cs[s][r + 0] = v.x;
        cs[s][r + 1] = v.y;
        cs[s][r + 2] = v.z;
        cs[s][r + 3] = v.w;
    }
    // load h (already transposed [r][b] in gmem, linear copy)
    #pragma unroll
    for (int i = tid; i < RNK * BATCH / 4; i += 64)
        ((float4*)&hs[0][0])[i] = ((const float4*)g_ht)[i];
    __syncthreads();

    const int sl = tid & 31;
    const int bg = tid >> 5;               // b = bg*16 .. bg*16+15
    unsigned long long acc[8];
    #pragma unroll
    for (int j = 0; j < 8; j++) acc[j] = 0ull;

    #pragma unroll 4
    for (int r = 0; r < RNK; r++) {
        unsigned long long cc = pack_dup(cs[sl][r]);
        const ulonglong2* hrow = (const ulonglong2*)(&hs[r][bg * 16]);
        #pragma unroll
        for (int q = 0; q < 4; q++) {
            ulonglong2 h2 = hrow[q];
            FMA2(acc[2 * q],     cc, h2.x);
            FMA2(acc[2 * q + 1], cc, h2.y);
        }
    }

    float b0 = beta[s0 + sl];
    #pragma unroll
    for (int j = 0; j < 8; j++) {
        float2 v = *(float2*)&acc[j];
        out[(size_t)(bg * 16 + 2 * j)     * SDIM + s0 + sl] = v.x + b0;
        out[(size_t)(bg * 16 + 2 * j + 1) * SDIM + s0 + sl] = v.y + b0;
    }
}

// ---------------- launcher ----------------------------------------------------
extern "C" void kernel_launch(void* const* d_in, const int* in_sizes, int n_in,
                              void* d_out, int out_size) {
    const float* x     = (const float*)d_in[0];
    const float* U     = (const float*)d_in[1];
    const float* C     = (const float*)d_in[2];
    const float* beta  = (const float*)d_in[3];
    const float* gamma = (const float*)d_in[4];
    const float* bnb   = (const float*)d_in[5];
    float* out = (float*)d_out;

    k_reduce<<<RED_BLOCKS, 256>>>(x);
    k_stats<<<1, 256>>>();
    k_normalize<<<NTOT / 4 / 256, 256>>>(x, gamma, bnb);
    dim3 g1(KSLICES, NDEG);
    k_gemm1<<<g1, 128>>>(U);
    dim3 gc(BATCH * RNK / 128, KSGRP);
    k_combine1<<<gc, 128>>>();
    k_combine2<<<BATCH * RNK / 512, 512>>>();
    k_gemm2<<<SDIM / STILE, 64>>>(C, beta, out);
}

// round 7
// speedup vs baseline: 1.1901x; 1.1901x over previous
#include <cuda_runtime.h>

#define BATCH   32
#define SDIM    65536
#define RNK     128
#define NDEG    4
#define KSLICES 256
#define KPER    (SDIM / KSLICES)   // 256  -> zs = 256*36*4 = 36,864 B (< 48KB static cap)
#define NTOT    (BATCH * SDIM)     // 2097152
#define RED_BLOCKS 256
#define STILE   32
#define KSGRP   8                  // combine stage-1 groups (32 slices each)
#define PF      8                  // U prefetch depth

// ---------------- scratch (device globals; no runtime allocation) -------------
__device__ float g_stats[2];
__device__ float g_bsum[RED_BLOCKS];
__device__ float g_bsq[RED_BLOCKS];
__device__ float g_partial[NDEG * KSLICES * BATCH * RNK];     // split-K partials (16MB)
__device__ float g_part2[NDEG * KSGRP * BATCH * RNK];         // stage-1 sums
__device__ float g_ht[RNK * BATCH];                           // h transposed [r][b]

// ---------------- packed f32x2 helpers ----------------------------------------
__device__ __forceinline__ unsigned long long pack_dup(float v) {
    unsigned long long r;
    asm("mov.b64 %0, {%1, %1};" : "=l"(r) : "f"(v));
    return r;
}
#define FMA2(acc, a, b) \
    asm("fma.rn.f32x2 %0, %1, %2, %0;" : "+l"(acc) : "l"(a), "l"(b))

// ---------------- 1) per-block reduction of sum / sumsq ----------------------
__global__ void k_reduce(const float* __restrict__ x) {
    float s = 0.f, sq = 0.f;
    const float4* x4 = (const float4*)x;
    const int stride = gridDim.x * blockDim.x;
    for (int i = blockIdx.x * blockDim.x + threadIdx.x; i < NTOT / 4; i += stride) {
        float4 v = x4[i];
        s  += (v.x + v.y) + (v.z + v.w);
        sq += (v.x * v.x + v.y * v.y) + (v.z * v.z + v.w * v.w);
    }
    #pragma unroll
    for (int o = 16; o > 0; o >>= 1) {
        s  += __shfl_down_sync(0xffffffffu, s,  o);
        sq += __shfl_down_sync(0xffffffffu, sq, o);
    }
    __shared__ float ss[8], sqq[8];
    int w = threadIdx.x >> 5, lane = threadIdx.x & 31;
    if (lane == 0) { ss[w] = s; sqq[w] = sq; }
    __syncthreads();
    if (threadIdx.x == 0) {
        float S = 0.f, Q = 0.f;
        #pragma unroll
        for (int j = 0; j < 8; j++) { S += ss[j]; Q += sqq[j]; }
        g_bsum[blockIdx.x] = S;
        g_bsq[blockIdx.x]  = Q;
    }
}

// ---------------- 2) final stats ----------------------------------------------
__global__ void k_stats() {
    int t = threadIdx.x;                 // 256 threads
    float s = g_bsum[t], q = g_bsq[t];
    #pragma unroll
    for (int o = 16; o > 0; o >>= 1) {
        s += __shfl_down_sync(0xffffffffu, s, o);
        q += __shfl_down_sync(0xffffffffu, q, o);
    }
    __shared__ float ss[8], qq[8];
    int w = t >> 5, lane = t & 31;
    if (lane == 0) { ss[w] = s; qq[w] = q; }
    __syncthreads();
    if (t == 0) {
        float S = 0.f, Q = 0.f;
        #pragma unroll
        for (int j = 0; j < 8; j++) { S += ss[j]; Q += qq[j]; }
        g_stats[0] = S;
        g_stats[1] = Q;
    }
}

// ---------------- 3) GEMM1 (split-K, packed f32x2, fused BN, U prefetch) ------
// 128 threads = one per rank column r. 16 u64 accumulators = 32 batches paired.
// BN affine fused into the z staging (reads x directly, no g_z round trip).
// U prefetched 8 deep into registers -> 8 outstanding 128B loads per warp.
__global__ __launch_bounds__(128, 4) void k_gemm1(const float* __restrict__ U,
                                                  const float* __restrict__ x,
                                                  const float* __restrict__ gamma,
                                                  const float* __restrict__ bnb) {
    __shared__ __align__(16) float zs[KPER][36];        // 36,864 B static
    const int n   = blockIdx.y;
    const int ks  = blockIdx.x;
    const int tid = threadIdx.x;

    {   // stage normalized x -> zs[k][b]  (coalesced global reads, fused BN)
        const float inv_n = 1.f / (float)NTOT;
        float mean = g_stats[0] * inv_n;
        float var  = g_stats[1] * inv_n - mean * mean;
        float a = gamma[0] * rsqrtf(var + 1e-5f);
        float c = bnb[0] - mean * a;
        const float* xsrc = x + ks * KPER;
        #pragma unroll
        for (int i = tid; i < BATCH * KPER; i += 128) {
            int b = i >> 8;            // KPER = 256
            int k = i & (KPER - 1);
            zs[k][b] = fmaf(xsrc[(size_t)b * SDIM + k], a, c);
        }
    }
    __syncthreads();

    const float* Up = U + ((size_t)n * SDIM + (size_t)ks * KPER) * RNK + tid;
    unsigned long long acc[BATCH / 2];
    #pragma unroll
    for (int j = 0; j < BATCH / 2; j++) acc[j] = 0ull;

    // rolling prefetch ring of U values; rolling pointer (no per-k IMAD chain)
    float upf[PF];
    #pragma unroll
    for (int j = 0; j < PF; j++) upf[j] = Up[(size_t)j * RNK];
    const float* Upk = Up + (size_t)PF * RNK;

    for (int k0 = 0; k0 < KPER - PF; k0 += PF) {        // 31 iters of 8
        #pragma unroll
        for (int j = 0; j < PF; j++) {
            unsigned long long uu = pack_dup(upf[j]);
            upf[j] = Upk[(size_t)j * RNK];              // prefetch k0+PF+j
            const ulonglong2* zrow = (const ulonglong2*)(&zs[k0 + j][0]);
            #pragma unroll
            for (int q = 0; q < 8; q++) {
                ulonglong2 z2 = zrow[q];
                FMA2(acc[2 * q],     uu, z2.x);
                FMA2(acc[2 * q + 1], uu, z2.y);
            }
        }
        Upk += (size_t)PF * RNK;
    }
    #pragma unroll
    for (int j = 0; j < PF; j++) {                      // drain last 8
        unsigned long long uu = pack_dup(upf[j]);
        const ulonglong2* zrow = (const ulonglong2*)(&zs[KPER - PF + j][0]);
        #pragma unroll
        for (int q = 0; q < 8; q++) {
            ulonglong2 z2 = zrow[q];
            FMA2(acc[2 * q],     uu, z2.x);
            FMA2(acc[2 * q + 1], uu, z2.y);
        }
    }

    float* outp = g_partial + (size_t)(n * KSLICES + ks) * (BATCH * RNK) + tid;
    #pragma unroll
    for (int j = 0; j < BATCH / 2; j++) {
        float2 v = *(float2*)&acc[j];
        outp[(2 * j) * RNK]     = v.x;
        outp[(2 * j + 1) * RNK] = v.y;
    }
}

// ---------------- 4a) combine stage 1: sum 32 k-slices ------------------------
__global__ void k_combine1() {
    const int idx = blockIdx.x * blockDim.x + threadIdx.x;  // 0..4095 (b*RNK+r)
    const int g   = blockIdx.y;                              // 0..KSGRP-1
    #pragma unroll
    for (int n = 0; n < NDEG; n++) {
        const float* p = g_partial + idx
                       + (size_t)(n * KSLICES + g * (KSLICES / KSGRP)) * (BATCH * RNK);
        float t = 0.f;
        #pragma unroll 8
        for (int ks = 0; ks < KSLICES / KSGRP; ks++)
            t += p[(size_t)ks * (BATCH * RNK)];
        g_part2[(n * KSGRP + g) * (BATCH * RNK) + idx] = t;
    }
}

// ---------------- 4b) combine stage 2 + degree-4 CCP recurrence ---------------
__global__ void k_combine2() {
    int idx = blockIdx.x * blockDim.x + threadIdx.x;    // 4096 threads = b*RNK+r
    float t[NDEG];
    #pragma unroll
    for (int n = 0; n < NDEG; n++) {
        float s = 0.f;
        #pragma unroll
        for (int g = 0; g < KSGRP; g++)
            s += g_part2[(n * KSGRP + g) * (BATCH * RNK) + idx];
        t[n] = s;
    }
    float h = t[0];
    h = fmaf(t[1], h, h);
    h = fmaf(t[2], h, h);
    h = fmaf(t[3], h, h);
    int b = idx >> 7, r = idx & 127;
    g_ht[r * BATCH + b] = h;                            // store transposed [r][b]
}

// ---------------- 5) GEMM2: out[b][s] = sum_r h[b][r]*C[s][r] + beta[s] -------
// Block: 32 s x all 32 b, 64 threads: sl=tid&31 (one s), bg=tid>>5 (16 b each).
// Static smem ~32.9 KB. Packed f32x2 along b.
__global__ __launch_bounds__(64) void k_gemm2(const float* __restrict__ Cm,
                                              const float* __restrict__ beta,
                                              float* __restrict__ out) {
    __shared__ __align__(16) float cs[STILE][129];      // padded, conflict-free
    __shared__ __align__(16) float hs[RNK][BATCH];      // [r][b], broadcast reads
    const int tid = threadIdx.x;
    const int s0  = blockIdx.x * STILE;

    // load C tile (coalesced float4)
    #pragma unroll
    for (int i = tid; i < STILE * RNK / 4; i += 64) {
        int s  = i >> 5;                   // 32 float4 per 128-float row
        int rq = i & 31;
        float4 v = ((const float4*)(Cm + (size_t)(s0 + s) * RNK))[rq];
        int r = rq * 4;
        cs[s][r + 0] = v.x;
        cs[s][r + 1] = v.y;
        cs[s][r + 2] = v.z;
        cs[s][r + 3] = v.w;
    }
    // load h (already transposed [r][b] in gmem, linear copy)
    #pragma unroll
    for (int i = tid; i < RNK * BATCH / 4; i += 64)
        ((float4*)&hs[0][0])[i] = ((const float4*)g_ht)[i];
    __syncthreads();

    const int sl = tid & 31;
    const int bg = tid >> 5;               // b = bg*16 .. bg*16+15
    unsigned long long acc[8];
    #pragma unroll
    for (int j = 0; j < 8; j++) acc[j] = 0ull;

    #pragma unroll 8
    for (int r = 0; r < RNK; r++) {
        unsigned long long cc = pack_dup(cs[sl][r]);
        const ulonglong2* hrow = (const ulonglong2*)(&hs[r][bg * 16]);
        #pragma unroll
        for (int q = 0; q < 4; q++) {
            ulonglong2 h2 = hrow[q];
            FMA2(acc[2 * q],     cc, h2.x);
            FMA2(acc[2 * q + 1], cc, h2.y);
        }
    }

    float b0 = beta[s0 + sl];
    #pragma unroll
    for (int j = 0; j < 8; j++) {
        float2 v = *(float2*)&acc[j];
        out[(size_t)(bg * 16 + 2 * j)     * SDIM + s0 + sl] = v.x + b0;
        out[(size_t)(bg * 16 + 2 * j + 1) * SDIM + s0 + sl] = v.y + b0;
    }
}

// ---------------- launcher ----------------------------------------------------
extern "C" void kernel_launch(void* const* d_in, const int* in_sizes, int n_in,
                              void* d_out, int out_size) {
    const float* x     = (const float*)d_in[0];
    const float* U     = (const float*)d_in[1];
    const float* C     = (const float*)d_in[2];
    const float* beta  = (const float*)d_in[3];
    const float* gamma = (const float*)d_in[4];
    const float* bnb   = (const float*)d_in[5];
    float* out = (float*)d_out;

    k_reduce<<<RED_BLOCKS, 256>>>(x);
    k_stats<<<1, 256>>>();
    dim3 g1(KSLICES, NDEG);
    k_gemm1<<<g1, 128>>>(U, x, gamma, bnb);
    dim3 gc(BATCH * RNK / 128, KSGRP);
    k_combine1<<<gc, 128>>>();
    k_combine2<<<BATCH * RNK / 512, 512>>>();
    k_gemm2<<<SDIM / STILE, 64>>>(C, beta, out);
}

// round 9
// speedup vs baseline: 1.3447x; 1.1300x over previous
#include <cuda_runtime.h>

#define BATCH   32
#define SDIM    65536
#define RNK     128
#define NDEG    4
#define KSLICES 256
#define KPER    (SDIM / KSLICES)   // 256  -> zs = 256*36*4 = 36,864 B (< 48KB static cap)
#define NTOT    (BATCH * SDIM)     // 2097152
#define RED_BLOCKS 256
#define STILE   32
#define KSGRP   32                 // combine stage-1 groups (8 slices each)
#define PF      8                  // U prefetch depth (float4 ring)

// ---------------- scratch (device globals; no runtime allocation) -------------
__device__ float g_stats[2];
__device__ float g_bsum[RED_BLOCKS];
__device__ float g_bsq[RED_BLOCKS];
__device__ float g_partial[NDEG * KSLICES * BATCH * RNK];     // split-K partials (16MB)
__device__ float g_part2[NDEG * KSGRP * BATCH * RNK];         // stage-1 sums (2MB)
__device__ float g_ht[RNK * BATCH];                           // h transposed [r][b]

// ---------------- packed f32x2 helpers ----------------------------------------
__device__ __forceinline__ unsigned long long pack_dup(float v) {
    unsigned long long r;
    asm("mov.b64 %0, {%1, %1};" : "=l"(r) : "f"(v));
    return r;
}
#define FMA2(acc, a, b) \
    asm("fma.rn.f32x2 %0, %1, %2, %0;" : "+l"(acc) : "l"(a), "l"(b))

// ---------------- 1) per-block reduction of sum / sumsq ----------------------
__global__ void k_reduce(const float* __restrict__ x) {
    float s = 0.f, sq = 0.f;
    const float4* x4 = (const float4*)x;
    const int stride = gridDim.x * blockDim.x;
    for (int i = blockIdx.x * blockDim.x + threadIdx.x; i < NTOT / 4; i += stride) {
        float4 v = x4[i];
        s  += (v.x + v.y) + (v.z + v.w);
        sq += (v.x * v.x + v.y * v.y) + (v.z * v.z + v.w * v.w);
    }
    #pragma unroll
    for (int o = 16; o > 0; o >>= 1) {
        s  += __shfl_down_sync(0xffffffffu, s,  o);
        sq += __shfl_down_sync(0xffffffffu, sq, o);
    }
    __shared__ float ss[8], sqq[8];
    int w = threadIdx.x >> 5, lane = threadIdx.x & 31;
    if (lane == 0) { ss[w] = s; sqq[w] = sq; }
    __syncthreads();
    if (threadIdx.x == 0) {
        float S = 0.f, Q = 0.f;
        #pragma unroll
        for (int j = 0; j < 8; j++) { S += ss[j]; Q += sqq[j]; }
        g_bsum[blockIdx.x] = S;
        g_bsq[blockIdx.x]  = Q;
    }
}

// ---------------- 2) final stats ----------------------------------------------
__global__ void k_stats() {
    int t = threadIdx.x;                 // 256 threads
    float s = g_bsum[t], q = g_bsq[t];
    #pragma unroll
    for (int o = 16; o > 0; o >>= 1) {
        s += __shfl_down_sync(0xffffffffu, s, o);
        q += __shfl_down_sync(0xffffffffu, q, o);
    }
    __shared__ float ss[8], qq[8];
    int w = t >> 5, lane = t & 31;
    if (lane == 0) { ss[w] = s; qq[w] = q; }
    __syncthreads();
    if (t == 0) {
        float S = 0.f, Q = 0.f;
        #pragma unroll
        for (int j = 0; j < 8; j++) { S += ss[j]; Q += qq[j]; }
        g_stats[0] = S;
        g_stats[1] = Q;
    }
}

// ---------------- 3) GEMM1: 4 ranks x 8 batches per thread --------------------
// tid = bt*32 + rt: rt -> ranks 4rt..4rt+3 (one LDG.128 of U per k),
// bt -> batches 8bt..8bt+7 (two LDS.128 of z per k).
// Per k: 16 FMA2 + 2 LDS + 1 LDG + 4 mov  (FMA-pipe bound).
__global__ __launch_bounds__(128, 4) void k_gemm1(const float* __restrict__ U,
                                                  const float* __restrict__ x,
                                                  const float* __restrict__ gamma,
                                                  const float* __restrict__ bnb) {
    __shared__ __align__(16) float zs[KPER][36];        // 36,864 B static
    const int n   = blockIdx.y;
    const int ks  = blockIdx.x;
    const int tid = threadIdx.x;
    const int rt  = tid & 31;          // rank tile: 4*rt
    const int bt  = tid >> 5;          // batch tile: 8*bt

    {   // stage normalized x -> zs[k][b]  (coalesced global reads, fused BN)
        const float inv_n = 1.f / (float)NTOT;
        float mean = g_stats[0] * inv_n;
        float var  = g_stats[1] * inv_n - mean * mean;
        float a = gamma[0] * rsqrtf(var + 1e-5f);
        float c = bnb[0] - mean * a;
        const float* xsrc = x + ks * KPER;
        #pragma unroll
        for (int i = tid; i < BATCH * KPER; i += 128) {
            int b = i >> 8;            // KPER = 256
            int k = i & (KPER - 1);
            zs[k][b] = fmaf(xsrc[(size_t)b * SDIM + k], a, c);
        }
    }
    __syncthreads();

    const float* Up = U + ((size_t)n * SDIM + (size_t)ks * KPER) * RNK + 4 * rt;
    // acc[j][p]: rank 4rt+j, batches (8bt+2p, 8bt+2p+1) packed
    unsigned long long acc[4][4];
    #pragma unroll
    for (int j = 0; j < 4; j++)
        #pragma unroll
        for (int p = 0; p < 4; p++) acc[j][p] = 0ull;

    // rolling prefetch ring of U float4s
    float4 upf[PF];
    #pragma unroll
    for (int j = 0; j < PF; j++) upf[j] = *(const float4*)(Up + (size_t)j * RNK);
    const float* Upk = Up + (size_t)PF * RNK;

    for (int k0 = 0; k0 < KPER - PF; k0 += PF) {        // 31 iters of 8
        #pragma unroll
        for (int j = 0; j < PF; j++) {
            float4 u4 = upf[j];
            upf[j] = *(const float4*)(Upk + (size_t)j * RNK);
            const ulonglong2* zrow = (const ulonglong2*)(&zs[k0 + j][bt * 8]);
            ulonglong2 za = zrow[0], zb = zrow[1];
            unsigned long long u0 = pack_dup(u4.x), u1 = pack_dup(u4.y);
            unsigned long long u2 = pack_dup(u4.z), u3 = pack_dup(u4.w);
            FMA2(acc[0][0], u0, za.x);  FMA2(acc[0][1], u0, za.y);
            FMA2(acc[0][2], u0, zb.x);  FMA2(acc[0][3], u0, zb.y);
            FMA2(acc[1][0], u1, za.x);  FMA2(acc[1][1], u1, za.y);
            FMA2(acc[1][2], u1, zb.x);  FMA2(acc[1][3], u1, zb.y);
            FMA2(acc[2][0], u2, za.x);  FMA2(acc[2][1], u2, za.y);
            FMA2(acc[2][2], u2, zb.x);  FMA2(acc[2][3], u2, zb.y);
            FMA2(acc[3][0], u3, za.x);  FMA2(acc[3][1], u3, za.y);
            FMA2(acc[3][2], u3, zb.x);  FMA2(acc[3][3], u3, zb.y);
        }
        Upk += (size_t)PF * RNK;
    }
    #pragma unroll
    for (int j = 0; j < PF; j++) {                      // drain last 8
        float4 u4 = upf[j];
        const ulonglong2* zrow = (const ulonglong2*)(&zs[KPER - PF + j][bt * 8]);
        ulonglong2 za = zrow[0], zb = zrow[1];
        unsigned long long u0 = pack_dup(u4.x), u1 = pack_dup(u4.y);
        unsigned long long u2 = pack_dup(u4.z), u3 = pack_dup(u4.w);
        FMA2(acc[0][0], u0, za.x);  FMA2(acc[0][1], u0, za.y);
        FMA2(acc[0][2], u0, zb.x);  FMA2(acc[0][3], u0, zb.y);
        FMA2(acc[1][0], u1, za.x);  FMA2(acc[1][1], u1, za.y);
        FMA2(acc[1][2], u1, zb.x);  FMA2(acc[1][3], u1, zb.y);
        FMA2(acc[2][0], u2, za.x);  FMA2(acc[2][1], u2, za.y);
        FMA2(acc[2][2], u2, zb.x);  FMA2(acc[2][3], u2, zb.y);
        FMA2(acc[3][0], u3, za.x);  FMA2(acc[3][1], u3, za.y);
        FMA2(acc[3][2], u3, zb.x);  FMA2(acc[3][3], u3, zb.y);
    }

    // write [n][ks][b][r]: per batch-pair, build float4 across the 4 ranks
    float* outp = g_partial + (size_t)(n * KSLICES + ks) * (BATCH * RNK);
    #pragma unroll
    for (int p = 0; p < 4; p++) {
        float2 v0 = *(float2*)&acc[0][p];
        float2 v1 = *(float2*)&acc[1][p];
        float2 v2 = *(float2*)&acc[2][p];
        float2 v3 = *(float2*)&acc[3][p];
        float4 lo = make_float4(v0.x, v1.x, v2.x, v3.x);   // batch 8bt+2p
        float4 hi = make_float4(v0.y, v1.y, v2.y, v3.y);   // batch 8bt+2p+1
        *(float4*)(outp + (size_t)(bt * 8 + 2 * p)     * RNK + 4 * rt) = lo;
        *(float4*)(outp + (size_t)(bt * 8 + 2 * p + 1) * RNK + 4 * rt) = hi;
    }
}

// ---------------- 4a) combine stage 1: float4, 8 slices per group -------------
__global__ void k_combine1() {
    const int idx4 = blockIdx.x * blockDim.x + threadIdx.x;  // 0..1023 float4
    const int g    = blockIdx.y;                              // 0..KSGRP-1
    const float4* p4 = (const float4*)g_partial;
    float4* o4 = (float4*)g_part2;
    #pragma unroll
    for (int n = 0; n < NDEG; n++) {
        float4 t = make_float4(0.f, 0.f, 0.f, 0.f);
        const float4* p = p4 + (size_t)(n * KSLICES + g * (KSLICES / KSGRP)) * 1024 + idx4;
        #pragma unroll
        for (int s = 0; s < KSLICES / KSGRP; s++) {
            float4 v = p[(size_t)s * 1024];
            t.x += v.x; t.y += v.y; t.z += v.z; t.w += v.w;
        }
        o4[(size_t)(n * KSGRP + g) * 1024 + idx4] = t;
    }
}

// ---------------- 4b) combine stage 2 + degree-4 CCP recurrence ---------------
__global__ void k_combine2() {
    int idx = blockIdx.x * blockDim.x + threadIdx.x;    // 4096 threads = b*RNK+r
    float t[NDEG];
    #pragma unroll
    for (int n = 0; n < NDEG; n++) {
        float s = 0.f;
        #pragma unroll 8
        for (int g = 0; g < KSGRP; g++)
            s += g_part2[(size_t)(n * KSGRP + g) * (BATCH * RNK) + idx];
        t[n] = s;
    }
    float h = t[0];
    h = fmaf(t[1], h, h);
    h = fmaf(t[2], h, h);
    h = fmaf(t[3], h, h);
    int b = idx >> 7, r = idx & 127;
    g_ht[r * BATCH + b] = h;                            // store transposed [r][b]
}

// ---------------- 5) GEMM2: out[b][s] = sum_r h[b][r]*C[s][r] + beta[s] -------
__global__ __launch_bounds__(64) void k_gemm2(const float* __restrict__ Cm,
                                              const float* __restrict__ beta,
                                              float* __restrict__ out) {
    __shared__ __align__(16) float cs[STILE][129];      // padded, conflict-free
    __shared__ __align__(16) float hs[RNK][BATCH];      // [r][b], broadcast reads
    const int tid = threadIdx.x;
    const int s0  = blockIdx.x * STILE;

    #pragma unroll
    for (int i = tid; i < STILE * RNK / 4; i += 64) {
        int s  = i >> 5;
        int rq = i & 31;
        float4 v = ((const float4*)(Cm + (size_t)(s0 + s) * RNK))[rq];
        int r = rq * 4;
        cs[s][r + 0] = v.x;
        cs[s][r + 1] = v.y;
        cs[s][r + 2] = v.z;
        cs[s][r + 3] = v.w;
    }
    #pragma unroll
    for (int i = tid; i < RNK * BATCH / 4; i += 64)
        ((float4*)&hs[0][0])[i] = ((const float4*)g_ht)[i];
    __syncthreads();

    const int sl = tid & 31;
    const int bg = tid >> 5;               // b = bg*16 .. bg*16+15
    unsigned long long acc[8];
    #pragma unroll
    for (int j = 0; j < 8; j++) acc[j] = 0ull;

    #pragma unroll 8
    for (int r = 0; r < RNK; r++) {
        unsigned long long cc = pack_dup(cs[sl][r]);
        const ulonglong2* hrow = (const ulonglong2*)(&hs[r][bg * 16]);
        #pragma unroll
        for (int q = 0; q < 4; q++) {
            ulonglong2 h2 = hrow[q];
            FMA2(acc[2 * q],     cc, h2.x);
            FMA2(acc[2 * q + 1], cc, h2.y);
        }
    }

    float b0 = beta[s0 + sl];
    #pragma unroll
    for (int j = 0; j < 8; j++) {
        float2 v = *(float2*)&acc[j];
        out[(size_t)(bg * 16 + 2 * j)     * SDIM + s0 + sl] = v.x + b0;
        out[(size_t)(bg * 16 + 2 * j + 1) * SDIM + s0 + sl] = v.y + b0;
    }
}

// ---------------- launcher ----------------------------------------------------
extern "C" void kernel_launch(void* const* d_in, const int* in_sizes, int n_in,
                              void* d_out, int out_size) {
    const float* x     = (const float*)d_in[0];
    const float* U     = (const float*)d_in[1];
    const float* C     = (const float*)d_in[2];
    const float* beta  = (const float*)d_in[3];
    const float* gamma = (const float*)d_in[4];
    const float* bnb   = (const float*)d_in[5];
    float* out = (float*)d_out;

    k_reduce<<<RED_BLOCKS, 256>>>(x);
    k_stats<<<1, 256>>>();
    dim3 g1(KSLICES, NDEG);
    k_gemm1<<<g1, 128>>>(U, x, gamma, bnb);
    dim3 gc(8, KSGRP);                       // 1024 float4-idx / 128 threads
    k_combine1<<<gc, 128>>>();
    k_combine2<<<BATCH * RNK / 512, 512>>>();
    k_gemm2<<<SDIM / STILE, 64>>>(C, beta, out);
}